// round 7
// baseline (speedup 1.0000x reference)
#include <cuda_runtime.h>

#define BATCH 2048
#define ISIZE 2048
#define OSIZE 2048
#define NIN   6
#define KTAB  64

typedef unsigned long long ull;

// Static scratch: transposed x, xT[m][b]  (16 MB)
__device__ float g_xT[(size_t)ISIZE * BATCH];

__device__ __forceinline__ ull pack2(float lo, float hi) {
    ull r;
    asm("mov.b64 %0, {%1, %2};" : "=l"(r) : "f"(lo), "f"(hi));
    return r;
}
__device__ __forceinline__ ull fma2(ull a, ull b, ull c) {
    ull r;
    asm("fma.rn.f32x2 %0, %1, %2, %3;" : "=l"(r) : "l"(a), "l"(b), "l"(c));
    return r;
}
__device__ __forceinline__ ull mul2(ull a, ull b) {
    ull r;
    asm("mul.rn.f32x2 %0, %1, %2;" : "=l"(r) : "l"(a), "l"(b));
    return r;
}
__device__ __forceinline__ float2 unpack2(ull v) {
    float2 f;
    asm("mov.b64 {%0, %1}, %2;" : "=f"(f.x), "=f"(f.y) : "l"(v));
    return f;
}

// ---------------------------------------------------------------------------
// Kernel 1: transpose x [BATCH][ISIZE] -> g_xT [ISIZE][BATCH]
// ---------------------------------------------------------------------------
__global__ void transpose_kernel(const float* __restrict__ x) {
    __shared__ float tile[32][33];
    int bx = blockIdx.x * 32;   // input-feature base
    int by = blockIdx.y * 32;   // batch base
    int tx = threadIdx.x, ty = threadIdx.y;
#pragma unroll
    for (int j = 0; j < 32; j += 8)
        tile[ty + j][tx] = x[(size_t)(by + ty + j) * ISIZE + bx + tx];
    __syncthreads();
#pragma unroll
    for (int j = 0; j < 32; j += 8)
        g_xT[(size_t)(bx + ty + j) * BATCH + by + tx] = tile[tx][ty + j];
}

// ---------------------------------------------------------------------------
// Kernel 2: LUT evaluation.
//   CTA tile: 8 outputs x 256 batches (128 threads, 2 batches/thread, f32x2).
//   Grid = 256 x 8 = 2048 CTAs (~2 waves, occ ~44% vs 20% at OT=32).
//   Quad coeffs stored NON-duplicated as float4 (a,d0,d1,d01): 1 LDS.128
//   broadcast (2 L1 wavefronts) per quad, lane-duplication done with ALU
//   movs (alu pipe has headroom; L1 was the binding resource).
//   Levels 2-5 are the lerp tree (f32x2 throughout).
// ---------------------------------------------------------------------------
#define OT      8
#define THREADS 128
#define BT      (2 * THREADS)
#define NQ      (KTAB / 4)   // 16 quads

__global__ __launch_bounds__(THREADS)
void lut_kernel(const float* __restrict__ table,
                const void* __restrict__ mraw,
                float* __restrict__ out) {
    __shared__ __align__(16) float4 s_c[OT][NQ];   // (a, d0, d1, d01)
    __shared__ int s_off[OT][NIN];
    __shared__ int s_is64;

    const int tid   = threadIdx.x;
    const int obase = blockIdx.x * OT;
    const int bbase = blockIdx.y * BT;

    // Detect mapping dtype: int64 values < 2048 => odd 32-bit words are 0.
    const int* w32 = (const int*)mraw;
    if (tid == 0) {
        int z = 1;
#pragma unroll
        for (int i = 1; i < 16; i += 2) z &= (w32[i] == 0);
        s_is64 = z;
    }
    __syncthreads();
    const int is64 = s_is64;

    // Gather offsets.
    if (tid < OT * NIN) {
        int idx = (obase + tid / NIN) * NIN + (tid % NIN);
        int m = is64 ? (int)((const long long*)mraw)[idx] : w32[idx];
        s_off[tid / NIN][tid % NIN] = m * BATCH + bbase;
    }

    // Sigmoid + bilinear Mobius coefficients per quad (one item per thread).
    {
        int o = tid >> 4, q = tid & (NQ - 1);   // OT*NQ == THREADS == 128
        const float* t = table + (size_t)(obase + o) * KTAB + 4 * q;
        float s0 = 1.0f / (1.0f + __expf(-t[0]));   // x0=0, x1=0
        float s1 = 1.0f / (1.0f + __expf(-t[1]));   // x0=1, x1=0
        float s2 = 1.0f / (1.0f + __expf(-t[2]));   // x0=0, x1=1
        float s3 = 1.0f / (1.0f + __expf(-t[3]));   // x0=1, x1=1
        s_c[o][q] = make_float4(s0, s1 - s0, s2 - s0, s3 - s1 - s2 + s0);
    }
    __syncthreads();

    const ull NEG1 = pack2(-1.0f, -1.0f);
    const int bl = 2 * tid;

    float rlo[OT], rhi[OT];

#pragma unroll
    for (int o = 0; o < OT; o++) {
        // Gather 6 packed x-pairs (coalesced LDG.64 from transposed x).
        ull xv[NIN];
#pragma unroll
        for (int i = 0; i < NIN; i++)
            xv[i] = *(const ull*)(g_xT + s_off[o][i] + bl);

        const ull t01 = mul2(xv[0], xv[1]);

        // Levels 0-1 fused: 16 bilinear quads, 3 FFMA2 each.
        ull acc[NQ];
#pragma unroll
        for (int q = 0; q < NQ; q++) {
            float4 c = s_c[o][q];                 // 1 LDS.128 broadcast
            ull A   = pack2(c.x, c.x);
            ull D0  = pack2(c.y, c.y);
            ull D1  = pack2(c.z, c.z);
            ull D01 = pack2(c.w, c.w);
            ull r = fma2(xv[0], D0, A);           // a + x0*d0
            r     = fma2(xv[1], D1, r);           //   + x1*d1
            acc[q] = fma2(t01, D01, r);           //   + x0x1*d01
        }

        // Levels 2-5: lerp tree over 16 values.
#pragma unroll
        for (int lvl = 2; lvl < 6; lvl++) {
            const int n = KTAB >> (lvl + 1);
#pragma unroll
            for (int k = 0; k < n; k++) {
                ull d = fma2(acc[2 * k], NEG1, acc[2 * k + 1]);  // b - a
                acc[k] = fma2(xv[lvl], d, acc[2 * k]);            // a + x*(b-a)
            }
        }

        float2 r = unpack2(acc[0]);
        rlo[o] = r.x;
        rhi[o] = r.y;
    }

    // 32B contiguous per batch row (two float4 stores per row).
    float4* p0 = (float4*)(out + (size_t)(bbase + bl) * OSIZE + obase);
    float4* p1 = (float4*)(out + (size_t)(bbase + bl + 1) * OSIZE + obase);
    p0[0] = make_float4(rlo[0], rlo[1], rlo[2], rlo[3]);
    p0[1] = make_float4(rlo[4], rlo[5], rlo[6], rlo[7]);
    p1[0] = make_float4(rhi[0], rhi[1], rhi[2], rhi[3]);
    p1[1] = make_float4(rhi[4], rhi[5], rhi[6], rhi[7]);
}

// ---------------------------------------------------------------------------
extern "C" void kernel_launch(void* const* d_in, const int* in_sizes, int n_in,
                              void* d_out, int out_size) {
    const float* x     = (const float*)d_in[0];
    const float* table = (const float*)d_in[1];
    const void*  mraw  = d_in[2];
    float*       out   = (float*)d_out;

    (void)in_sizes; (void)n_in; (void)out_size;

    transpose_kernel<<<dim3(ISIZE / 32, BATCH / 32), dim3(32, 8)>>>(x);
    lut_kernel<<<dim3(OSIZE / OT, BATCH / BT), THREADS>>>(table, mraw, out);
}

// round 8
// speedup vs baseline: 1.6741x; 1.6741x over previous
#include <cuda_runtime.h>

#define BATCH 2048
#define ISIZE 2048
#define OSIZE 2048
#define NIN   6
#define KTAB  64

typedef unsigned long long ull;

// Static scratch: transposed x, xT[m][b]  (16 MB)
__device__ float g_xT[(size_t)ISIZE * BATCH];

__device__ __forceinline__ ull pack2(float lo, float hi) {
    ull r;
    asm("mov.b64 %0, {%1, %2};" : "=l"(r) : "f"(lo), "f"(hi));
    return r;
}
__device__ __forceinline__ ull fma2(ull a, ull b, ull c) {
    ull r;
    asm("fma.rn.f32x2 %0, %1, %2, %3;" : "=l"(r) : "l"(a), "l"(b), "l"(c));
    return r;
}
__device__ __forceinline__ ull mul2(ull a, ull b) {
    ull r;
    asm("mul.rn.f32x2 %0, %1, %2;" : "=l"(r) : "l"(a), "l"(b));
    return r;
}
__device__ __forceinline__ float2 unpack2(ull v) {
    float2 f;
    asm("mov.b64 {%0, %1}, %2;" : "=f"(f.x), "=f"(f.y) : "l"(v));
    return f;
}

// ---------------------------------------------------------------------------
// Kernel 1: transpose x [BATCH][ISIZE] -> g_xT [ISIZE][BATCH]
// ---------------------------------------------------------------------------
__global__ void transpose_kernel(const float* __restrict__ x) {
    __shared__ float tile[32][33];
    int bx = blockIdx.x * 32;
    int by = blockIdx.y * 32;
    int tx = threadIdx.x, ty = threadIdx.y;
#pragma unroll
    for (int j = 0; j < 32; j += 8)
        tile[ty + j][tx] = x[(size_t)(by + ty + j) * ISIZE + bx + tx];
    __syncthreads();
#pragma unroll
    for (int j = 0; j < 32; j += 8)
        g_xT[(size_t)(bx + ty + j) * BATCH + by + tx] = tile[tx][ty + j];
}

// ---------------------------------------------------------------------------
// Kernel 2: LUT evaluation.
//   CTA tile: 4 outputs x 512 batches. 128 threads; each thread evaluates
//   TWO f32x2 batch-pairs (4 batches: bl and bl+256) so every coefficient
//   LDS.128 broadcast is amortized over 2 pairs (L1 was the binding pipe).
//   Levels 0-1: bilinear quads with precomputed Mobius coeffs (a,d0,d1,d01).
//   Levels 2-5: depth-first lerp tree (3-deep stack => low register count).
//   Grid = 512 x 4 = 2048 CTAs.
// ---------------------------------------------------------------------------
#define OT      4
#define THREADS 128
#define BT      512
#define NQ      (KTAB / 4)   // 16 quads

#define LERP2(dst, a, b, xx) do {            \
    ull d__ = fma2((a), NEG1, (b));          \
    (dst) = fma2((xx), d__, (a));            \
} while (0)

#define QUADE(qidx, r0, r1) do {                                   \
    float4 c = s_c[o][(qidx)];                                     \
    ull A   = pack2(c.x, c.x);                                     \
    ull D0  = pack2(c.y, c.y);                                     \
    ull D1  = pack2(c.z, c.z);                                     \
    ull D01 = pack2(c.w, c.w);                                     \
    (r0) = fma2(t01a, D01, fma2(xv0[1], D1, fma2(xv0[0], D0, A))); \
    (r1) = fma2(t01b, D01, fma2(xv1[1], D1, fma2(xv1[0], D0, A))); \
} while (0)

__global__ __launch_bounds__(THREADS)
void lut_kernel(const float* __restrict__ table,
                const void* __restrict__ mraw,
                float* __restrict__ out) {
    __shared__ __align__(16) float4 s_c[OT][NQ];   // (a, d0, d1, d01)
    __shared__ int s_off[OT][NIN];
    __shared__ int s_is64;

    const int tid   = threadIdx.x;
    const int obase = blockIdx.x * OT;
    const int bbase = blockIdx.y * BT;

    // Detect mapping dtype: int64 values < 2048 => odd 32-bit words are 0.
    const int* w32 = (const int*)mraw;
    if (tid == 0) {
        int z = 1;
#pragma unroll
        for (int i = 1; i < 16; i += 2) z &= (w32[i] == 0);
        s_is64 = z;
    }
    __syncthreads();
    const int is64 = s_is64;

    if (tid < OT * NIN) {
        int idx = (obase + tid / NIN) * NIN + (tid % NIN);
        int m = is64 ? (int)((const long long*)mraw)[idx] : w32[idx];
        s_off[tid / NIN][tid % NIN] = m * BATCH + bbase;
    }

    if (tid < OT * NQ) {
        int o = tid >> 4, q = tid & (NQ - 1);
        const float* t = table + (size_t)(obase + o) * KTAB + 4 * q;
        float s0 = 1.0f / (1.0f + __expf(-t[0]));   // x0=0, x1=0
        float s1 = 1.0f / (1.0f + __expf(-t[1]));   // x0=1, x1=0
        float s2 = 1.0f / (1.0f + __expf(-t[2]));   // x0=0, x1=1
        float s3 = 1.0f / (1.0f + __expf(-t[3]));   // x0=1, x1=1
        s_c[o][q] = make_float4(s0, s1 - s0, s2 - s0, s3 - s1 - s2 + s0);
    }
    __syncthreads();

    const ull NEG1 = pack2(-1.0f, -1.0f);
    const int bl = 2 * tid;   // pair0 batch offset; pair1 at bl + 256

    float r0lo[OT], r0hi[OT], r1lo[OT], r1hi[OT];

#pragma unroll
    for (int o = 0; o < OT; o++) {
        // Gather packed x-pairs for both batch-pairs (coalesced LDG.64).
        ull xv0[NIN], xv1[NIN];
#pragma unroll
        for (int i = 0; i < NIN; i++) {
            const float* base = g_xT + s_off[o][i] + bl;
            xv0[i] = *(const ull*)base;
            xv1[i] = *(const ull*)(base + 256);
        }
        const ull t01a = mul2(xv0[0], xv0[1]);
        const ull t01b = mul2(xv1[0], xv1[1]);

        // Depth-first evaluation: 16 quads -> lerp tree levels 2..5.
        ull s2a, s2b, s3a, s3b, s4a, s4b, ra, rb;
#pragma unroll
        for (int g = 0; g < 8; g++) {
            ull u0, u1, v0, v1, e0, e1;
            QUADE(2 * g,     u0, u1);
            QUADE(2 * g + 1, v0, v1);
            LERP2(e0, u0, v0, xv0[2]);
            LERP2(e1, u1, v1, xv1[2]);
            if ((g & 1) == 0) { s2a = e0; s2b = e1; }
            else {
                ull f0, f1;
                LERP2(f0, s2a, e0, xv0[3]);
                LERP2(f1, s2b, e1, xv1[3]);
                if ((g & 2) == 0) { s3a = f0; s3b = f1; }
                else {
                    ull h0, h1;
                    LERP2(h0, s3a, f0, xv0[4]);
                    LERP2(h1, s3b, f1, xv1[4]);
                    if ((g & 4) == 0) { s4a = h0; s4b = h1; }
                    else {
                        LERP2(ra, s4a, h0, xv0[5]);
                        LERP2(rb, s4b, h1, xv1[5]);
                    }
                }
            }
        }

        float2 fa = unpack2(ra), fb = unpack2(rb);
        r0lo[o] = fa.x; r0hi[o] = fa.y;
        r1lo[o] = fb.x; r1hi[o] = fb.y;
    }

    // 16B contiguous per batch row, 4 rows per thread.
    *(float4*)(out + (size_t)(bbase + bl)           * OSIZE + obase) =
        make_float4(r0lo[0], r0lo[1], r0lo[2], r0lo[3]);
    *(float4*)(out + (size_t)(bbase + bl + 1)       * OSIZE + obase) =
        make_float4(r0hi[0], r0hi[1], r0hi[2], r0hi[3]);
    *(float4*)(out + (size_t)(bbase + bl + 256)     * OSIZE + obase) =
        make_float4(r1lo[0], r1lo[1], r1lo[2], r1lo[3]);
    *(float4*)(out + (size_t)(bbase + bl + 256 + 1) * OSIZE + obase) =
        make_float4(r1hi[0], r1hi[1], r1hi[2], r1hi[3]);
}

// ---------------------------------------------------------------------------
extern "C" void kernel_launch(void* const* d_in, const int* in_sizes, int n_in,
                              void* d_out, int out_size) {
    const float* x     = (const float*)d_in[0];
    const float* table = (const float*)d_in[1];
    const void*  mraw  = d_in[2];
    float*       out   = (float*)d_out;

    (void)in_sizes; (void)n_in; (void)out_size;

    transpose_kernel<<<dim3(ISIZE / 32, BATCH / 32), dim3(32, 8)>>>(x);
    lut_kernel<<<dim3(OSIZE / OT, BATCH / BT), THREADS>>>(table, mraw, out);
}